// round 3
// baseline (speedup 1.0000x reference)
#include <cuda_runtime.h>
#include <cstdint>

// ============================================================================
// out[b,c] = 8192 - sx[b] - sw[c] + 2*cross[b,c]
//   cross = (weighted x bits u8) @ (w bits s8)^T : M=256, N=4096, K=8192
//   integer mma.sync (u8 x s8 -> s32), exact; compiles on plain sm_100
//   (tcgen05 rejected by harness ptxas target).
// ============================================================================

#define THRESH 0.05f

static constexpr int MDIM = 256;
static constexpr int NDIM = 4096;
static constexpr int FDIM = 4096;     // input feature dim
static constexpr int KDIM = 8192;     // bit dim = 2*FDIM (bytes in u8/s8)

// ---------------- scratch (device globals: no allocation allowed) -----------
static __device__ __align__(128) uint8_t g_xa[(size_t)MDIM * KDIM]; // 2 MB  weighted x bits
static __device__ __align__(128) uint8_t g_wb[(size_t)NDIM * KDIM]; // 32 MB w bits 0/1
static __device__ float g_sx[MDIM];
static __device__ float g_sw[NDIM];

// ---------------- PTX helpers ------------------------------------------------
__device__ __forceinline__ uint32_t smem_u32(const void* p) {
    uint32_t a;
    asm("{ .reg .u64 t; cvta.to.shared.u64 t, %1; cvt.u32.u64 %0, t; }"
        : "=r"(a) : "l"(p));
    return a;
}

__device__ __forceinline__ void cp16(uint32_t dst, const void* src) {
    asm volatile("cp.async.cg.shared.global [%0], [%1], 16;"
                 :: "r"(dst), "l"(src) : "memory");
}
#define CP_COMMIT() asm volatile("cp.async.commit_group;" ::: "memory")
#define CP_WAIT2()  asm volatile("cp.async.wait_group 2;" ::: "memory")

// D (s32) += A(u8, row-major m16xk32) * B(s8, col-major k32xn8)
__device__ __forceinline__ void mma_u8s8(int32_t* c, const uint32_t* a,
                                         const uint32_t* b) {
    asm volatile(
        "mma.sync.aligned.m16n8k32.row.col.s32.u8.s8.s32 "
        "{%0,%1,%2,%3}, {%4,%5,%6,%7}, {%8,%9}, {%0,%1,%2,%3};"
        : "+r"(c[0]), "+r"(c[1]), "+r"(c[2]), "+r"(c[3])
        : "r"(a[0]), "r"(a[1]), "r"(a[2]), "r"(a[3]), "r"(b[0]), "r"(b[1]));
}

// ============================================================================
// Quantization: ternary -> 2-bit (neg,pos) per feature, byte-weight layout.
// Feature f (within group of 4): neg/pos weights (128,64),(32,16),(8,4),(2,1).
// x stores the WEIGHTED bit value (u8); w stores raw bit 0/1 (s8).
// Both accumulate the weighted row sum.
// ============================================================================

template <bool WEIGHTED>
__device__ __forceinline__ uint32_t qpack2(float v0, float v1, float wn0,
                                           float wp0, float wn1, float wp1,
                                           float& s) {
    uint32_t b0 = (v0 <= -THRESH) ? (uint32_t)wn0 : 0u;
    uint32_t b1 = (v0 >=  THRESH) ? (uint32_t)wp0 : 0u;
    uint32_t b2 = (v1 <= -THRESH) ? (uint32_t)wn1 : 0u;
    uint32_t b3 = (v1 >=  THRESH) ? (uint32_t)wp1 : 0u;
    s += (float)(b0 + b1 + b2 + b3);
    if (!WEIGHTED) {
        b0 = b0 ? 1u : 0u; b1 = b1 ? 1u : 0u;
        b2 = b2 ? 1u : 0u; b3 = b3 ? 1u : 0u;
    }
    return b0 | (b1 << 8) | (b2 << 16) | (b3 << 24);
}

template <bool WEIGHTED>
__device__ __forceinline__ void quant_row(const float* __restrict__ src_row,
                                          uint8_t* __restrict__ dst_row,
                                          float* __restrict__ sum_out) {
    const float4* src = (const float4*)src_row;
    uint2* dst = (uint2*)(void*)dst_row;
    float s = 0.0f;
    for (int i = threadIdx.x; i < FDIM / 4; i += 256) {
        float4 v = src[i];
        uint2 o;
        o.x = qpack2<WEIGHTED>(v.x, v.y, 128.f, 64.f, 32.f, 16.f, s);
        o.y = qpack2<WEIGHTED>(v.z, v.w,   8.f,  4.f,  2.f,  1.f, s);
        dst[i] = o;
    }
    __shared__ float red[256];
    red[threadIdx.x] = s;
    __syncthreads();
    for (int off = 128; off > 0; off >>= 1) {
        if (threadIdx.x < off) red[threadIdx.x] += red[threadIdx.x + off];
        __syncthreads();
    }
    if (threadIdx.x == 0) *sum_out = red[0];
}

__global__ void __launch_bounds__(256) quant_x_kernel(const float* __restrict__ x) {
    const int row = blockIdx.x;
    quant_row<true>(x + (size_t)row * FDIM, g_xa + (size_t)row * KDIM, &g_sx[row]);
}

__global__ void __launch_bounds__(256) quant_w_kernel(const float* __restrict__ w) {
    const int row = blockIdx.x;
    quant_row<false>(w + (size_t)row * FDIM, g_wb + (size_t)row * KDIM, &g_sw[row]);
}

// ============================================================================
// int8 GEMM: BM=64, BN=128, BK=128 (bytes); 4-stage cp.async pipeline.
// 256 threads = 8 warps in 2(M) x 4(N); warp tile 32x32.
// SMEM row stride 144 B: banks (36r+q) mod 32 = 4r+q -> conflict-free quads.
// ============================================================================

static constexpr int BM = 64;
static constexpr int BN = 128;
static constexpr int BK = 128;                  // bytes (k elements)
static constexpr int KITERS = KDIM / BK;        // 64
static constexpr int NSTAGES = 4;
static constexpr int STRIDE = 144;              // smem row stride (bytes)
static constexpr int A_SZ = BM * STRIDE;        // 9216
static constexpr int B_SZ = BN * STRIDE;        // 18432
static constexpr int STAGE = A_SZ + B_SZ;       // 27648
static constexpr int SMEM_BYTES = NSTAGES * STAGE;  // 110592

__global__ void __launch_bounds__(256, 1)
qgemm_kernel(float* __restrict__ out) {
    extern __shared__ char smem[];
    const uint32_t sb = smem_u32(smem);
    const int tid = threadIdx.x;
    const int wid = tid >> 5;
    const int lane = tid & 31;
    const int wm = wid & 1;          // 0..1  (M)
    const int wn = wid >> 1;         // 0..3  (N)
    const int n0 = blockIdx.x * BN;
    const int m0 = blockIdx.y * BM;

    // ---- cp.async assignments: A 512 chunks (2/thr), B 1024 chunks (4/thr)
    const uint8_t* gA = g_xa;
    const uint8_t* gB = g_wb;
    const uint8_t* a_src[2]; uint32_t a_dst[2];
#pragma unroll
    for (int i = 0; i < 2; i++) {
        int q = tid + i * 256;
        int r = q >> 3, kc = q & 7;
        a_src[i] = gA + (size_t)(m0 + r) * KDIM + kc * 16;
        a_dst[i] = (uint32_t)(r * STRIDE + kc * 16);
    }
    const uint8_t* b_src[4]; uint32_t b_dst[4];
#pragma unroll
    for (int i = 0; i < 4; i++) {
        int q = tid + i * 256;
        int r = q >> 3, kc = q & 7;
        b_src[i] = gB + (size_t)(n0 + r) * KDIM + kc * 16;
        b_dst[i] = (uint32_t)(A_SZ + r * STRIDE + kc * 16);
    }

    auto load_stage = [&](int s) {
        const uint32_t base = sb + (uint32_t)(s & (NSTAGES - 1)) * STAGE;
        const int ko = s * BK;
#pragma unroll
        for (int i = 0; i < 2; i++) cp16(base + a_dst[i], a_src[i] + ko);
#pragma unroll
        for (int i = 0; i < 4; i++) cp16(base + b_dst[i], b_src[i] + ko);
    };

    // ---- accumulators
    int32_t c[2][4][4];
#pragma unroll
    for (int mf = 0; mf < 2; mf++)
#pragma unroll
        for (int nf = 0; nf < 4; nf++)
#pragma unroll
            for (int r = 0; r < 4; r++) c[mf][nf][r] = 0;

    // fragment read offsets
    const int arow = wm * 32 + (lane >> 2);
    const int brow = wn * 32 + (lane >> 2);
    const int coff = (lane & 3) * 4;

    // ---- prologue: 3 stages in flight
#pragma unroll
    for (int s = 0; s < NSTAGES - 1; ++s) { load_stage(s); CP_COMMIT(); }

    for (int it = 0; it < KITERS; ++it) {
        CP_WAIT2();
        __syncthreads();
        const char* sbase = smem + (it & (NSTAGES - 1)) * STAGE;
        const char* sA = sbase;
        const char* sB = sbase + A_SZ;

#pragma unroll
        for (int ks = 0; ks < BK / 32; ++ks) {       // 4 k-steps of 32
            const int kb = ks * 32;
            uint32_t a[2][4];
#pragma unroll
            for (int mf = 0; mf < 2; mf++) {
                const char* p = sA + (arow + mf * 16) * STRIDE + kb + coff;
                a[mf][0] = *(const uint32_t*)(p);
                a[mf][1] = *(const uint32_t*)(p + 8 * STRIDE);
                a[mf][2] = *(const uint32_t*)(p + 16);
                a[mf][3] = *(const uint32_t*)(p + 8 * STRIDE + 16);
            }
            uint32_t b[4][2];
#pragma unroll
            for (int nf = 0; nf < 4; nf++) {
                const char* p = sB + (brow + nf * 8) * STRIDE + kb + coff;
                b[nf][0] = *(const uint32_t*)(p);
                b[nf][1] = *(const uint32_t*)(p + 16);
            }
#pragma unroll
            for (int mf = 0; mf < 2; mf++)
#pragma unroll
                for (int nf = 0; nf < 4; nf++)
                    mma_u8s8(c[mf][nf], a[mf], b[nf]);
        }

        const int pf = it + NSTAGES - 1;
        if (pf < KITERS) load_stage(pf);
        CP_COMMIT();
    }

    // ---- epilogue: out = 8192 - sx[m] - sw[n] + 2*c  (exact integers)
#pragma unroll
    for (int mf = 0; mf < 2; mf++) {
        const int r0 = m0 + wm * 32 + mf * 16 + (lane >> 2);
        const float bx0 = 8192.0f - g_sx[r0];
        const float bx1 = 8192.0f - g_sx[r0 + 8];
#pragma unroll
        for (int nf = 0; nf < 4; nf++) {
            const int col = n0 + wn * 32 + nf * 8 + (lane & 3) * 2;
            const float sw0 = g_sw[col], sw1 = g_sw[col + 1];
            float2 v0, v1;
            v0.x = bx0 - sw0 + 2.0f * (float)c[mf][nf][0];
            v0.y = bx0 - sw1 + 2.0f * (float)c[mf][nf][1];
            v1.x = bx1 - sw0 + 2.0f * (float)c[mf][nf][2];
            v1.y = bx1 - sw1 + 2.0f * (float)c[mf][nf][3];
            *(float2*)(out + (size_t)r0 * NDIM + col) = v0;
            *(float2*)(out + (size_t)(r0 + 8) * NDIM + col) = v1;
        }
    }
}

// ============================================================================
// launcher
// ============================================================================
extern "C" void kernel_launch(void* const* d_in, const int* in_sizes, int n_in,
                              void* d_out, int out_size) {
    (void)in_sizes; (void)n_in; (void)out_size;
    const float* x = (const float*)d_in[0];   // [256, 4096]
    const float* w = (const float*)d_in[1];   // [4096, 4096]
    float* out = (float*)d_out;               // [256, 4096]

    quant_x_kernel<<<MDIM, 256>>>(x);
    quant_w_kernel<<<NDIM, 256>>>(w);

    cudaFuncSetAttribute(qgemm_kernel,
                         cudaFuncAttributeMaxDynamicSharedMemorySize, SMEM_BYTES);
    dim3 grid(NDIM / BN, MDIM / BM);          // (32, 4) = 128 CTAs
    qgemm_kernel<<<grid, 256, SMEM_BYTES>>>(out);
}

// round 4
// speedup vs baseline: 1.1000x; 1.1000x over previous
#include <cuda_runtime.h>
#include <cstdint>

// ============================================================================
// out[b,c] = 8192 - sx[b] - sw[c] + 2*cross[b,c]
//   cross = (weighted x bits u8) @ (w bits s8)^T : M=256, N=4096, K=8192
//   integer mma.sync (u8 x s8 -> s32), exact; plain sm_100 target (no tcgen05).
// ============================================================================

#define THRESH 0.05f

static constexpr int MDIM = 256;
static constexpr int NDIM = 4096;
static constexpr int FDIM = 4096;     // input feature dim
static constexpr int KDIM = 8192;     // bit dim = 2*FDIM (bytes in u8/s8)

// ---------------- scratch (device globals: no allocation allowed) -----------
static __device__ __align__(128) uint8_t g_xa[(size_t)MDIM * KDIM]; // 2 MB
static __device__ __align__(128) uint8_t g_wb[(size_t)NDIM * KDIM]; // 32 MB
static __device__ float g_sx[MDIM];
static __device__ float g_sw[NDIM];

// ---------------- PTX helpers ------------------------------------------------
__device__ __forceinline__ uint32_t smem_u32(const void* p) {
    uint32_t a;
    asm("{ .reg .u64 t; cvta.to.shared.u64 t, %1; cvt.u32.u64 %0, t; }"
        : "=r"(a) : "l"(p));
    return a;
}

__device__ __forceinline__ void cp16(uint32_t dst, const void* src) {
    asm volatile("cp.async.cg.shared.global [%0], [%1], 16;"
                 :: "r"(dst), "l"(src) : "memory");
}
#define CP_COMMIT() asm volatile("cp.async.commit_group;" ::: "memory")
#define CP_WAIT2()  asm volatile("cp.async.wait_group 2;" ::: "memory")

// D (s32) += A(u8, row-major m16xk32) * B(s8, col-major k32xn8)
__device__ __forceinline__ void mma_u8s8(int32_t* c, const uint32_t* a,
                                         const uint32_t* b) {
    asm volatile(
        "mma.sync.aligned.m16n8k32.row.col.s32.u8.s8.s32 "
        "{%0,%1,%2,%3}, {%4,%5,%6,%7}, {%8,%9}, {%0,%1,%2,%3};"
        : "+r"(c[0]), "+r"(c[1]), "+r"(c[2]), "+r"(c[3])
        : "r"(a[0]), "r"(a[1]), "r"(a[2]), "r"(a[3]), "r"(b[0]), "r"(b[1]));
}

__device__ __forceinline__ void ldsm4(uint32_t& r0, uint32_t& r1, uint32_t& r2,
                                      uint32_t& r3, uint32_t addr) {
    asm volatile("ldmatrix.sync.aligned.m8n8.x4.shared.b16 {%0,%1,%2,%3}, [%4];"
                 : "=r"(r0), "=r"(r1), "=r"(r2), "=r"(r3) : "r"(addr));
}

// ============================================================================
// Fused quantization: ternary -> 2-bit (neg,pos), byte-weight layout.
// Feature f (mod 4): neg/pos weights (128,64),(32,16),(8,4),(2,1).
// x rows (blocks 0..255): weighted bit values (u8).  w rows: raw bits 0/1.
// ============================================================================

template <bool WEIGHTED>
__device__ __forceinline__ uint32_t qpack2(float v0, float v1, float wn0,
                                           float wp0, float wn1, float wp1,
                                           float& s) {
    uint32_t b0 = (v0 <= -THRESH) ? (uint32_t)wn0 : 0u;
    uint32_t b1 = (v0 >=  THRESH) ? (uint32_t)wp0 : 0u;
    uint32_t b2 = (v1 <= -THRESH) ? (uint32_t)wn1 : 0u;
    uint32_t b3 = (v1 >=  THRESH) ? (uint32_t)wp1 : 0u;
    s += (float)(b0 + b1 + b2 + b3);
    if (!WEIGHTED) {
        b0 = b0 ? 1u : 0u; b1 = b1 ? 1u : 0u;
        b2 = b2 ? 1u : 0u; b3 = b3 ? 1u : 0u;
    }
    return b0 | (b1 << 8) | (b2 << 16) | (b3 << 24);
}

template <bool WEIGHTED>
__device__ __forceinline__ void quant_row(const float* __restrict__ src_row,
                                          uint8_t* __restrict__ dst_row,
                                          float* __restrict__ sum_out) {
    const float4* src = (const float4*)src_row;
    uint2* dst = (uint2*)(void*)dst_row;
    float s = 0.0f;
    // FDIM/4 = 1024 chunks, 256 threads -> exactly 4 per thread; batch loads.
    float4 v[4];
#pragma unroll
    for (int j = 0; j < 4; j++) v[j] = src[threadIdx.x + j * 256];
#pragma unroll
    for (int j = 0; j < 4; j++) {
        uint2 o;
        o.x = qpack2<WEIGHTED>(v[j].x, v[j].y, 128.f, 64.f, 32.f, 16.f, s);
        o.y = qpack2<WEIGHTED>(v[j].z, v[j].w,   8.f,  4.f,  2.f,  1.f, s);
        dst[threadIdx.x + j * 256] = o;
    }
    __shared__ float red[256];
    red[threadIdx.x] = s;
    __syncthreads();
    for (int off = 128; off > 0; off >>= 1) {
        if (threadIdx.x < off) red[threadIdx.x] += red[threadIdx.x + off];
        __syncthreads();
    }
    if (threadIdx.x == 0) *sum_out = red[0];
}

__global__ void __launch_bounds__(256) quant_kernel(const float* __restrict__ x,
                                                    const float* __restrict__ w) {
    const int bid = blockIdx.x;
    if (bid < MDIM) {
        quant_row<true>(x + (size_t)bid * FDIM, g_xa + (size_t)bid * KDIM,
                        &g_sx[bid]);
    } else {
        const int row = bid - MDIM;
        quant_row<false>(w + (size_t)row * FDIM, g_wb + (size_t)row * KDIM,
                         &g_sw[row]);
    }
}

// ============================================================================
// int8 GEMM: BM=64, BN=128, BK=128 bytes; 4-stage cp.async; ldmatrix frags.
// 256 threads = 8 warps in 2(M) x 4(N); warp tile 32x32.
// SMEM row stride 144 B: ldmatrix 8-row x 16B pattern conflict-free
// (16B-bank = 9r mod 8 = r, all distinct).
// ============================================================================

static constexpr int BM = 64;
static constexpr int BN = 128;
static constexpr int BK = 128;                  // bytes (k elements)
static constexpr int KITERS = KDIM / BK;        // 64
static constexpr int NSTAGES = 4;
static constexpr int STRIDE = 144;              // smem row stride (bytes)
static constexpr int A_SZ = BM * STRIDE;        // 9216
static constexpr int B_SZ = BN * STRIDE;        // 18432
static constexpr int STAGE = A_SZ + B_SZ;       // 27648
static constexpr int SMEM_BYTES = NSTAGES * STAGE;  // 110592

__global__ void __launch_bounds__(256, 1)
qgemm_kernel(float* __restrict__ out) {
    extern __shared__ char smem[];
    const uint32_t sb = smem_u32(smem);
    const int tid = threadIdx.x;
    const int wid = tid >> 5;
    const int lane = tid & 31;
    const int wm = wid & 1;          // 0..1  (M)
    const int wn = wid >> 1;         // 0..3  (N)
    const int n0 = blockIdx.x * BN;
    const int m0 = blockIdx.y * BM;

    // ---- cp.async assignments: A 512 chunks (2/thr), B 1024 chunks (4/thr)
    const uint8_t* a_src[2]; uint32_t a_dst[2];
#pragma unroll
    for (int i = 0; i < 2; i++) {
        int q = tid + i * 256;
        int r = q >> 3, kc = q & 7;
        a_src[i] = g_xa + (size_t)(m0 + r) * KDIM + kc * 16;
        a_dst[i] = (uint32_t)(r * STRIDE + kc * 16);
    }
    const uint8_t* b_src[4]; uint32_t b_dst[4];
#pragma unroll
    for (int i = 0; i < 4; i++) {
        int q = tid + i * 256;
        int r = q >> 3, kc = q & 7;
        b_src[i] = g_wb + (size_t)(n0 + r) * KDIM + kc * 16;
        b_dst[i] = (uint32_t)(A_SZ + r * STRIDE + kc * 16);
    }

    auto load_stage = [&](int s) {
        const uint32_t base = sb + (uint32_t)(s & (NSTAGES - 1)) * STAGE;
        const int ko = s * BK;
#pragma unroll
        for (int i = 0; i < 2; i++) cp16(base + a_dst[i], a_src[i] + ko);
#pragma unroll
        for (int i = 0; i < 4; i++) cp16(base + b_dst[i], b_src[i] + ko);
    };

    // ---- ldmatrix per-lane base offsets (within a stage)
    const int g  = lane >> 3;        // matrix index 0..3
    const int lr = lane & 7;         // row within matrix
    uint32_t a_lds[2];
#pragma unroll
    for (int mf = 0; mf < 2; mf++)
        a_lds[mf] = (uint32_t)((wm * 32 + mf * 16 + lr + (g & 1) * 8) * STRIDE
                               + (g >> 1) * 16);
    uint32_t b_lds[2];
#pragma unroll
    for (int p = 0; p < 2; p++)      // covers nf = 2p, 2p+1
        b_lds[p] = (uint32_t)(A_SZ + (wn * 32 + p * 16 + lr + (g >> 1) * 8) * STRIDE
                              + (g & 1) * 16);

    // ---- accumulators
    int32_t c[2][4][4];
#pragma unroll
    for (int mf = 0; mf < 2; mf++)
#pragma unroll
        for (int nf = 0; nf < 4; nf++)
#pragma unroll
            for (int r = 0; r < 4; r++) c[mf][nf][r] = 0;

    // ---- prologue: 3 stages in flight
#pragma unroll
    for (int s = 0; s < NSTAGES - 1; ++s) { load_stage(s); CP_COMMIT(); }

    for (int it = 0; it < KITERS; ++it) {
        CP_WAIT2();
        __syncthreads();

        // Issue next stage's loads FIRST (its buffer, (it+3)&3 == (it-1)&3,
        // was released by the barrier above), so they overlap the math.
        const int pf = it + NSTAGES - 1;
        if (pf < KITERS) load_stage(pf);
        CP_COMMIT();

        const uint32_t sbase = sb + (uint32_t)(it & (NSTAGES - 1)) * STAGE;

#pragma unroll
        for (int ks = 0; ks < BK / 32; ++ks) {       // 4 k-steps of 32
            const uint32_t kb = ks * 32;
            uint32_t a[2][4];
#pragma unroll
            for (int mf = 0; mf < 2; mf++)
                ldsm4(a[mf][0], a[mf][1], a[mf][2], a[mf][3],
                      sbase + a_lds[mf] + kb);
            uint32_t b[4][2];
#pragma unroll
            for (int p = 0; p < 2; p++)
                ldsm4(b[2 * p][0], b[2 * p][1], b[2 * p + 1][0], b[2 * p + 1][1],
                      sbase + b_lds[p] + kb);
#pragma unroll
            for (int mf = 0; mf < 2; mf++)
#pragma unroll
                for (int nf = 0; nf < 4; nf++)
                    mma_u8s8(c[mf][nf], a[mf], b[nf]);
        }
    }

    // ---- epilogue: out = 8192 - sx[m] - sw[n] + 2*c  (exact integers)
#pragma unroll
    for (int mf = 0; mf < 2; mf++) {
        const int r0 = m0 + wm * 32 + mf * 16 + (lane >> 2);
        const float bx0 = 8192.0f - g_sx[r0];
        const float bx1 = 8192.0f - g_sx[r0 + 8];
#pragma unroll
        for (int nf = 0; nf < 4; nf++) {
            const int col = n0 + wn * 32 + nf * 8 + (lane & 3) * 2;
            const float sw0 = g_sw[col], sw1 = g_sw[col + 1];
            float2 v0, v1;
            v0.x = bx0 - sw0 + 2.0f * (float)c[mf][nf][0];
            v0.y = bx0 - sw1 + 2.0f * (float)c[mf][nf][1];
            v1.x = bx1 - sw0 + 2.0f * (float)c[mf][nf][2];
            v1.y = bx1 - sw1 + 2.0f * (float)c[mf][nf][3];
            *(float2*)(out + (size_t)r0 * NDIM + col) = v0;
            *(float2*)(out + (size_t)(r0 + 8) * NDIM + col) = v1;
        }
    }
}

// ============================================================================
// launcher
// ============================================================================
extern "C" void kernel_launch(void* const* d_in, const int* in_sizes, int n_in,
                              void* d_out, int out_size) {
    (void)in_sizes; (void)n_in; (void)out_size;
    const float* x = (const float*)d_in[0];   // [256, 4096]
    const float* w = (const float*)d_in[1];   // [4096, 4096]
    float* out = (float*)d_out;               // [256, 4096]

    quant_kernel<<<MDIM + NDIM, 256>>>(x, w);

    cudaFuncSetAttribute(qgemm_kernel,
                         cudaFuncAttributeMaxDynamicSharedMemorySize, SMEM_BYTES);
    dim3 grid(NDIM / BN, MDIM / BM);          // (32, 4) = 128 CTAs
    qgemm_kernel<<<grid, 256, SMEM_BYTES>>>(out);
}

// round 5
// speedup vs baseline: 1.1104x; 1.0095x over previous
#include <cuda_runtime.h>
#include <cstdint>

// ============================================================================
// out[b,c] = 8192 - sx[b] - sw[c] + 2*cross[b,c]
//   cross = (weighted x bits u8) @ (w bits s8)^T : M=256, N=4096, K=8192
//   integer mma.sync (u8 x s8 -> s32), exact; plain sm_100 target (no tcgen05).
// ============================================================================

#define THRESH 0.05f

static constexpr int MDIM = 256;
static constexpr int NDIM = 4096;
static constexpr int FDIM = 4096;     // input feature dim
static constexpr int KDIM = 8192;     // bit dim = 2*FDIM (bytes in u8/s8)

// ---------------- scratch (device globals: no allocation allowed) -----------
static __device__ __align__(128) uint8_t g_xa[(size_t)MDIM * KDIM]; // 2 MB
static __device__ __align__(128) uint8_t g_wb[(size_t)NDIM * KDIM]; // 32 MB
static __device__ float g_sx[MDIM];
static __device__ float g_sw[NDIM];

// ---------------- PTX helpers ------------------------------------------------
__device__ __forceinline__ uint32_t smem_u32(const void* p) {
    uint32_t a;
    asm("{ .reg .u64 t; cvta.to.shared.u64 t, %1; cvt.u32.u64 %0, t; }"
        : "=r"(a) : "l"(p));
    return a;
}

__device__ __forceinline__ void cp16(uint32_t dst, const void* src) {
    asm volatile("cp.async.cg.shared.global [%0], [%1], 16;"
                 :: "r"(dst), "l"(src) : "memory");
}
#define CP_COMMIT() asm volatile("cp.async.commit_group;" ::: "memory")
#define CP_WAIT2()  asm volatile("cp.async.wait_group 2;" ::: "memory")

// D (s32) += A(u8, row-major m16xk32) * B(s8, col-major k32xn8)
__device__ __forceinline__ void mma_u8s8(int32_t* c, const uint32_t* a,
                                         const uint32_t* b) {
    asm volatile(
        "mma.sync.aligned.m16n8k32.row.col.s32.u8.s8.s32 "
        "{%0,%1,%2,%3}, {%4,%5,%6,%7}, {%8,%9}, {%0,%1,%2,%3};"
        : "+r"(c[0]), "+r"(c[1]), "+r"(c[2]), "+r"(c[3])
        : "r"(a[0]), "r"(a[1]), "r"(a[2]), "r"(a[3]), "r"(b[0]), "r"(b[1]));
}

__device__ __forceinline__ void ldsm4(uint32_t& r0, uint32_t& r1, uint32_t& r2,
                                      uint32_t& r3, uint32_t addr) {
    asm volatile("ldmatrix.sync.aligned.m8n8.x4.shared.b16 {%0,%1,%2,%3}, [%4];"
                 : "=r"(r0), "=r"(r1), "=r"(r2), "=r"(r3) : "r"(addr));
}

// ============================================================================
// Fused quantization: ternary -> 2-bit (neg,pos), byte-weight layout.
// Feature f (mod 4): neg/pos weights (128,64),(32,16),(8,4),(2,1).
// x rows (blocks 0..255): weighted bit values (u8).  w rows: raw bits 0/1.
// ============================================================================

template <bool WEIGHTED>
__device__ __forceinline__ uint32_t qpack2(float v0, float v1, float wn0,
                                           float wp0, float wn1, float wp1,
                                           float& s) {
    uint32_t b0 = (v0 <= -THRESH) ? (uint32_t)wn0 : 0u;
    uint32_t b1 = (v0 >=  THRESH) ? (uint32_t)wp0 : 0u;
    uint32_t b2 = (v1 <= -THRESH) ? (uint32_t)wn1 : 0u;
    uint32_t b3 = (v1 >=  THRESH) ? (uint32_t)wp1 : 0u;
    s += (float)(b0 + b1 + b2 + b3);
    if (!WEIGHTED) {
        b0 = b0 ? 1u : 0u; b1 = b1 ? 1u : 0u;
        b2 = b2 ? 1u : 0u; b3 = b3 ? 1u : 0u;
    }
    return b0 | (b1 << 8) | (b2 << 16) | (b3 << 24);
}

template <bool WEIGHTED>
__device__ __forceinline__ void quant_row(const float* __restrict__ src_row,
                                          uint8_t* __restrict__ dst_row,
                                          float* __restrict__ sum_out) {
    const float4* src = (const float4*)src_row;
    uint2* dst = (uint2*)(void*)dst_row;
    float s = 0.0f;
    // FDIM/4 = 1024 chunks, 256 threads -> exactly 4 per thread; batch loads.
    float4 v[4];
#pragma unroll
    for (int j = 0; j < 4; j++) v[j] = src[threadIdx.x + j * 256];
#pragma unroll
    for (int j = 0; j < 4; j++) {
        uint2 o;
        o.x = qpack2<WEIGHTED>(v[j].x, v[j].y, 128.f, 64.f, 32.f, 16.f, s);
        o.y = qpack2<WEIGHTED>(v[j].z, v[j].w,   8.f,  4.f,  2.f,  1.f, s);
        dst[threadIdx.x + j * 256] = o;
    }
    __shared__ float red[256];
    red[threadIdx.x] = s;
    __syncthreads();
    for (int off = 128; off > 0; off >>= 1) {
        if (threadIdx.x < off) red[threadIdx.x] += red[threadIdx.x + off];
        __syncthreads();
    }
    if (threadIdx.x == 0) *sum_out = red[0];
}

__global__ void __launch_bounds__(256) quant_kernel(const float* __restrict__ x,
                                                    const float* __restrict__ w) {
    const int bid = blockIdx.x;
    if (bid < MDIM) {
        quant_row<true>(x + (size_t)bid * FDIM, g_xa + (size_t)bid * KDIM,
                        &g_sx[bid]);
    } else {
        const int row = bid - MDIM;
        quant_row<false>(w + (size_t)row * FDIM, g_wb + (size_t)row * KDIM,
                         &g_sw[row]);
    }
}

// ============================================================================
// int8 GEMM: BM=64, BN=128, BK=128 bytes; 4-stage cp.async; ldmatrix frags
// double-buffered across k-steps so LDSM latency overlaps MMA issue.
// 256 threads = 8 warps in 2(M) x 4(N); warp tile 32x32.
// SMEM row stride 144 B: ldmatrix 8-row x 16B pattern conflict-free.
// ============================================================================

static constexpr int BM = 64;
static constexpr int BN = 128;
static constexpr int BK = 128;                  // bytes (k elements)
static constexpr int KITERS = KDIM / BK;        // 64
static constexpr int NSTAGES = 4;
static constexpr int STRIDE = 144;              // smem row stride (bytes)
static constexpr int A_SZ = BM * STRIDE;        // 9216
static constexpr int B_SZ = BN * STRIDE;        // 18432
static constexpr int STAGE = A_SZ + B_SZ;       // 27648
static constexpr int SMEM_BYTES = NSTAGES * STAGE;  // 110592

__global__ void __launch_bounds__(256, 1)
qgemm_kernel(float* __restrict__ out) {
    extern __shared__ char smem[];
    const uint32_t sb = smem_u32(smem);
    const int tid = threadIdx.x;
    const int wid = tid >> 5;
    const int lane = tid & 31;
    const int wm = wid & 1;          // 0..1  (M)
    const int wn = wid >> 1;         // 0..3  (N)
    const int n0 = blockIdx.x * BN;
    const int m0 = blockIdx.y * BM;

    // ---- cp.async assignments: A 512 chunks (2/thr), B 1024 chunks (4/thr)
    const uint8_t* a_src[2]; uint32_t a_dst[2];
#pragma unroll
    for (int i = 0; i < 2; i++) {
        int q = tid + i * 256;
        int r = q >> 3, kc = q & 7;
        a_src[i] = g_xa + (size_t)(m0 + r) * KDIM + kc * 16;
        a_dst[i] = (uint32_t)(r * STRIDE + kc * 16);
    }
    const uint8_t* b_src[4]; uint32_t b_dst[4];
#pragma unroll
    for (int i = 0; i < 4; i++) {
        int q = tid + i * 256;
        int r = q >> 3, kc = q & 7;
        b_src[i] = g_wb + (size_t)(n0 + r) * KDIM + kc * 16;
        b_dst[i] = (uint32_t)(A_SZ + r * STRIDE + kc * 16);
    }

    auto load_stage = [&](int s) {
        const uint32_t base = sb + (uint32_t)(s & (NSTAGES - 1)) * STAGE;
        const int ko = s * BK;
#pragma unroll
        for (int i = 0; i < 2; i++) cp16(base + a_dst[i], a_src[i] + ko);
#pragma unroll
        for (int i = 0; i < 4; i++) cp16(base + b_dst[i], b_src[i] + ko);
    };

    // ---- ldmatrix per-lane base offsets (within a stage)
    const int g  = lane >> 3;        // matrix index 0..3
    const int lr = lane & 7;         // row within matrix
    uint32_t a_lds[2];
#pragma unroll
    for (int mf = 0; mf < 2; mf++)
        a_lds[mf] = (uint32_t)((wm * 32 + mf * 16 + lr + (g & 1) * 8) * STRIDE
                               + (g >> 1) * 16);
    uint32_t b_lds[2];
#pragma unroll
    for (int p = 0; p < 2; p++)      // covers nf = 2p, 2p+1
        b_lds[p] = (uint32_t)(A_SZ + (wn * 32 + p * 16 + lr + (g >> 1) * 8) * STRIDE
                              + (g & 1) * 16);

    // ---- accumulators + double-buffered fragments
    int32_t c[2][4][4];
#pragma unroll
    for (int mf = 0; mf < 2; mf++)
#pragma unroll
        for (int nf = 0; nf < 4; nf++)
#pragma unroll
            for (int r = 0; r < 4; r++) c[mf][nf][r] = 0;

    uint32_t a[2][2][4];   // [buf][mf][reg]
    uint32_t b[2][4][2];   // [buf][nf][reg]

    auto load_frags = [&](uint32_t sbase, int ks, int buf) {
        const uint32_t kb = (uint32_t)(ks * 32);
#pragma unroll
        for (int mf = 0; mf < 2; mf++)
            ldsm4(a[buf][mf][0], a[buf][mf][1], a[buf][mf][2], a[buf][mf][3],
                  sbase + a_lds[mf] + kb);
#pragma unroll
        for (int p = 0; p < 2; p++)
            ldsm4(b[buf][2 * p][0], b[buf][2 * p][1],
                  b[buf][2 * p + 1][0], b[buf][2 * p + 1][1],
                  sbase + b_lds[p] + kb);
    };

    // ---- prologue: 3 stages in flight
#pragma unroll
    for (int s = 0; s < NSTAGES - 1; ++s) { load_stage(s); CP_COMMIT(); }

    for (int it = 0; it < KITERS; ++it) {
        CP_WAIT2();
        __syncthreads();

        // Issue next stage's GMEM loads first (buffer (it+3)&3 == (it-1)&3
        // was released by the barrier), so they overlap this tile's math.
        const int pf = it + NSTAGES - 1;
        if (pf < KITERS) load_stage(pf);
        CP_COMMIT();

        const uint32_t sbase = sb + (uint32_t)(it & (NSTAGES - 1)) * STAGE;

        load_frags(sbase, 0, 0);
#pragma unroll
        for (int ks = 0; ks < BK / 32; ++ks) {     // 4 k-steps of 32
            const int cur = ks & 1;
            if (ks < BK / 32 - 1) load_frags(sbase, ks + 1, cur ^ 1);
#pragma unroll
            for (int mf = 0; mf < 2; mf++)
#pragma unroll
                for (int nf = 0; nf < 4; nf++)
                    mma_u8s8(c[mf][nf], a[cur][mf], b[cur][nf]);
        }
    }

    // ---- epilogue: out = 8192 - sx[m] - sw[n] + 2*c  (exact integers)
#pragma unroll
    for (int mf = 0; mf < 2; mf++) {
        const int r0 = m0 + wm * 32 + mf * 16 + (lane >> 2);
        const float bx0 = 8192.0f - g_sx[r0];
        const float bx1 = 8192.0f - g_sx[r0 + 8];
#pragma unroll
        for (int nf = 0; nf < 4; nf++) {
            const int col = n0 + wn * 32 + nf * 8 + (lane & 3) * 2;
            const float sw0 = g_sw[col], sw1 = g_sw[col + 1];
            float2 v0, v1;
            v0.x = bx0 - sw0 + 2.0f * (float)c[mf][nf][0];
            v0.y = bx0 - sw1 + 2.0f * (float)c[mf][nf][1];
            v1.x = bx1 - sw0 + 2.0f * (float)c[mf][nf][2];
            v1.y = bx1 - sw1 + 2.0f * (float)c[mf][nf][3];
            *(float2*)(out + (size_t)r0 * NDIM + col) = v0;
            *(float2*)(out + (size_t)(r0 + 8) * NDIM + col) = v1;
        }
    }
}

// ============================================================================
// launcher
// ============================================================================
extern "C" void kernel_launch(void* const* d_in, const int* in_sizes, int n_in,
                              void* d_out, int out_size) {
    (void)in_sizes; (void)n_in; (void)out_size;
    const float* x = (const float*)d_in[0];   // [256, 4096]
    const float* w = (const float*)d_in[1];   // [4096, 4096]
    float* out = (float*)d_out;               // [256, 4096]

    quant_kernel<<<MDIM + NDIM, 256>>>(x, w);

    cudaFuncSetAttribute(qgemm_kernel,
                         cudaFuncAttributeMaxDynamicSharedMemorySize, SMEM_BYTES);
    dim3 grid(NDIM / BN, MDIM / BM);          // (32, 4) = 128 CTAs
    qgemm_kernel<<<grid, 256, SMEM_BYTES>>>(out);
}